// round 10
// baseline (speedup 1.0000x reference)
#include <cuda_runtime.h>
#include <cuda_bf16.h>
#include <cstdint>

#define GD 160
#define GH 160
#define GW 160
#define CIN 32
#define COUT 64
#define NK 27
#define TILE_V 128
#define TGROUP 8              // tiles per CTA (8 TMEM accumulators)
#define NMAX 400000

#if defined(__CUDA_ARCH_FEAT_SM103_ALL) || defined(__CUDA_ARCH_FEAT_SM100_ALL) || defined(__CUDA_ARCH_FEAT_SM101_ALL)
#define HAS_TCGEN05 1
#else
#define HAS_TCGEN05 0
#endif

// ---------------- device scratch ----------------
__device__ int      g_grid[GD * GH * GW];        // voxel -> row index
__device__ uint32_t g_packF[NMAX * CIN];         // packed (bf16 hi | lo<<16)
__device__ uint32_t g_Bw[NK * 4096];             // 27 x 16KB pre-swizzled B (pass1+pass2)

// ---------------- helpers ----------------
__device__ __forceinline__ uint32_t smem_u32(const void* p) {
    uint32_t a;
    asm("{ .reg .u64 t; cvta.to.shared.u64 t, %1; cvt.u32.u64 %0, t; }" : "=r"(a) : "l"(p));
    return a;
}

__host__ __device__ __forceinline__ uint32_t swz128(uint32_t off) {
    return off ^ ((off >> 3) & 0x70);
}

// SMEM descriptor: SW128, version=1, SBO=64 (1024B), LBO=1 (16B)
__device__ __forceinline__ uint64_t make_desc(uint32_t addr) {
    const uint64_t base =
        (uint64_t(2) << 61) | (uint64_t(1) << 46) | (uint64_t(64) << 32) | (uint64_t(1) << 16);
    return base | ((uint64_t)(addr >> 4) & 0x3FFF);
}

#define MMA_IDESC 0x8100490u   // F32 accum, A=BF16, B=BF16, N=64, M=128

#if HAS_TCGEN05
__device__ __forceinline__ void mma_f16_ss(uint32_t d_tmem, uint64_t a_desc,
                                           uint64_t b_desc, uint32_t en) {
    asm volatile(
        "{\n\t"
        ".reg .pred p;\n\t"
        "setp.ne.u32 p, %5, 0;\n\t"
        "tcgen05.mma.cta_group::1.kind::f16 [%0], %1, %2, %3, {%4, %4, %4, %4}, p;\n\t"
        "}"
        :: "r"(d_tmem), "l"(a_desc), "l"(b_desc), "r"(MMA_IDESC), "r"(0u), "r"(en)
        : "memory");
}
#endif

#define MBARRIER_WAIT_PARITY(mbar, parity) do {                                   \
    uint32_t _m = (mbar); uint32_t _p = (parity); uint32_t _done;                  \
    asm volatile(                                                                  \
        "{\n\t.reg .pred p;\n\t"                                                   \
        "mbarrier.try_wait.parity.acquire.cta.shared::cta.b64 p, [%1], %2;\n\t"    \
        "selp.b32 %0, 1, 0, p;\n\t}"                                               \
        : "=r"(_done) : "r"(_m), "r"(_p) : "memory");                              \
    if (!_done) {                                                                  \
        asm volatile(                                                              \
            "{\n\t.reg .pred P1;\n\t"                                              \
            "WL_%=:\n\t"                                                           \
            "mbarrier.try_wait.parity.acquire.cta.shared::cta.b64 P1, [%0], %1, 0x989680;\n\t" \
            "@P1 bra.uni WD_%=;\n\t"                                               \
            "bra.uni WL_%=;\n\t"                                                   \
            "WD_%=:\n\t}"                                                          \
            :: "r"(_m), "r"(_p) : "memory");                                       \
    }                                                                              \
} while (0)

// ---------------- prep kernels ----------------
__global__ void init_grid_kernel() {
    int i = blockIdx.x * blockDim.x + threadIdx.x;
    int4* p = reinterpret_cast<int4*>(g_grid);
    const int total = (GD * GH * GW) / 4;
    if (i < total) p[i] = make_int4(-1, -1, -1, -1);
}

// Fused: pack features + scatter + pack weights.
__global__ void prep_kernel(const int* __restrict__ coors,
                            const float* __restrict__ feat,
                            const float* __restrict__ weight,
                            int n) {
    int i = blockIdx.x * blockDim.x + threadIdx.x;
    const int nF = n * CIN;
    if (i < nF) {
        float x = feat[i];
        __nv_bfloat16 hi = __float2bfloat16(x);
        float r = x - __bfloat162float(hi);
        __nv_bfloat16 lo = __float2bfloat16(r);
        g_packF[i] = (uint32_t)__bfloat16_as_ushort(hi) |
                     ((uint32_t)__bfloat16_as_ushort(lo) << 16);
        return;
    }
    i -= nF;
    if (i < n) {
        int z = coors[4 * i + 1];
        int y = coors[4 * i + 2];
        int x = coors[4 * i + 3];
        g_grid[(z * GH + y) * GW + x] = i;
        return;
    }
    i -= n;
    if (i < NK * COUT * CIN) {
        int k  = i / (COUT * CIN);
        int rr = i % (COUT * CIN);
        int nn = rr / CIN;   // cout (B row)
        int c  = rr % CIN;   // cin
        float w = weight[k * CIN * COUT + c * COUT + nn];
        __nv_bfloat16 hi = __float2bfloat16(w);
        float res = w - __bfloat162float(hi);
        __nv_bfloat16 lo = __float2bfloat16(res);
        uint32_t hb = __bfloat16_as_ushort(hi);
        uint32_t lb = __bfloat16_as_ushort(lo);
        uint32_t sw = swz128((uint32_t)(nn * 128 + c * 4));
        g_Bw[k * 4096 + (sw >> 2)]        = hb | (hb << 16); // pass1: hi,hi
        g_Bw[k * 4096 + 2048 + (sw >> 2)] = lb;              // pass2: lo,0
    }
}

// ---------------- main tensor-core kernel ----------------
// K-outer / tile-inner: each CTA owns 8 tiles (1024 voxels) with 8 TMEM
// accumulators (8 x 64 cols = 512). B(k) is TMA'd ONCE per 8 MMA-steps
// (L2 B-traffic / 8). Depth-2 A pipeline; LDG.128+STS.128 gather; lookup
// prefetched one step ahead. Dyn smem: A0[16K] A1[16K] B0[16K] B1[16K].
__global__ __launch_bounds__(256) void conv_tc_kernel(
    const int*   __restrict__ coors,
    const float* __restrict__ bias,
    float*       __restrict__ out,
    int n)
{
#if HAS_TCGEN05
    extern __shared__ uint32_t dynsmem[];
    __shared__ uint32_t sPack[TGROUP * TILE_V];   // packed z<<16|y<<8|x (0xFFFFFFFF = inactive)
    __shared__ int   sIdx[2][TILE_V];
    __shared__ float sBias[COUT];
    __shared__ uint32_t sTmem;
    __shared__ __align__(8) uint64_t sMbarMMA[2];
    __shared__ __align__(8) uint64_t sMbarTMA[2];

    const int tid = threadIdx.x;
    const int vBase = blockIdx.x * (TGROUP * TILE_V);

    const uint32_t rawBase = smem_u32(dynsmem);
    const uint32_t aAddr   = (rawBase + 1023u) & ~1023u;
    uint32_t* sT = dynsmem + ((aAddr - rawBase) >> 2);

    const uint32_t mbarM0 = smem_u32(&sMbarMMA[0]);
    const uint32_t mbarM1 = smem_u32(&sMbarMMA[1]);
    const uint32_t mbarT0 = smem_u32(&sMbarTMA[0]);
    const uint32_t mbarT1 = smem_u32(&sMbarTMA[1]);
    if (tid == 0) {
        asm volatile("mbarrier.init.shared.b64 [%0], 1;" :: "r"(mbarM0) : "memory");
        asm volatile("mbarrier.init.shared.b64 [%0], 1;" :: "r"(mbarM1) : "memory");
        asm volatile("mbarrier.init.shared.b64 [%0], 1;" :: "r"(mbarT0) : "memory");
        asm volatile("mbarrier.init.shared.b64 [%0], 1;" :: "r"(mbarT1) : "memory");
    }
    if (tid < COUT) sBias[tid] = bias[tid];

    // Load + pack coors for the CTA's 1024 voxels (z,y,x each < 160 -> 8 bits).
    #pragma unroll
    for (int j = 0; j < 4; j++) {
        int slot = j * 256 + tid;
        int v = vBase + slot;
        uint32_t p = 0xFFFFFFFFu;
        if (v < n) {
            uint32_t z = (uint32_t)coors[4 * v + 1];
            uint32_t y = (uint32_t)coors[4 * v + 2];
            uint32_t x = (uint32_t)coors[4 * v + 3];
            p = (z << 16) | (y << 8) | x;
        }
        sPack[slot] = p;
    }
    if (tid < 32) {
        uint32_t a = smem_u32(&sTmem);
        asm volatile("tcgen05.alloc.cta_group::1.sync.aligned.shared::cta.b32 [%0], %1;"
                     :: "r"(a), "r"(512u) : "memory");
        asm volatile("tcgen05.relinquish_alloc_permit.cta_group::1.sync.aligned;");
    }
    __syncthreads();

    // Prologue lookup for step 0 (k=0: dz=dy=dx=-1, tile 0).
    if (tid < TILE_V) {
        uint32_t p = sPack[tid];
        int z = (int)(p >> 16) - 1, y = (int)((p >> 8) & 0xFF) - 1, x = (int)(p & 0xFF) - 1;
        int idx = -1;
        if ((unsigned)z < GD && (unsigned)y < GH && (unsigned)x < GW)
            idx = g_grid[(z * GH + y) * GW + x];
        sIdx[0][tid] = idx;
    }
    __syncthreads();

    const uint32_t tmem = sTmem;
    int phM0 = 0, phM1 = 0;
    int phT0 = 0, phT1 = 0;

    const int S = NK * TGROUP;   // 216 steps
    for (int s = 0; s < S; s++) {
        const int st = s & 1;
        const int k  = s >> 3;
        const int t  = s & 7;
        const uint32_t aSm = aAddr + (st ? 16384u : 0u);
        const uint32_t bSm = aAddr + 32768u + ((k & 1) ? 16384u : 0u);

        // A-stage reuse guard: MMA(s-2) done.
        if (s >= 2) {
            if (st == 0) { MBARRIER_WAIT_PARITY(mbarM0, phM0 & 1); phM0++; }
            else         { MBARRIER_WAIT_PARITY(mbarM1, phM1 & 1); phM1++; }
        }

        // New k: kick B(k) TMA once (serves 8 steps).
        if (t == 0 && tid == 0) {
            const uint32_t mbT = (k & 1) ? mbarT1 : mbarT0;
            asm volatile(
                "mbarrier.arrive.expect_tx.shared.b64 _, [%0], %1;"
                :: "r"(mbT), "r"(16384u) : "memory");
            asm volatile(
                "cp.async.bulk.shared::cta.global.mbarrier::complete_tx::bytes "
                "[%0], [%1], %2, [%3];"
                :: "r"(bSm), "l"((const void*)(g_Bw + k * 4096)), "r"(16384u), "r"(mbT)
                : "memory");
        }

        // Vectorized gather (R7 style): 1024 uint4 slots, 4 per thread.
        uint4* aDst = reinterpret_cast<uint4*>(sT + ((aSm - aAddr) >> 2));
        const int* idxBuf = sIdx[st];
        #pragma unroll
        for (int ss = 0; ss < 4; ss++) {
            int slot = ss * 256 + tid;
            int v = slot >> 3;
            int q = slot & 7;
            int idx = idxBuf[v];
            uint4 val = make_uint4(0u, 0u, 0u, 0u);
            if (idx >= 0)
                val = reinterpret_cast<const uint4*>(g_packF)[idx * 8 + q];
            aDst[v * 8 + (q ^ (v & 7))] = val;
        }

        // Prefetch lookup for step s+1.
        if (s + 1 < S && tid < TILE_V) {
            const int s1 = s + 1;
            const int k1 = s1 >> 3, t1 = s1 & 7;
            const int dz = k1 / 9 - 1, dy = (k1 / 3) % 3 - 1, dx = k1 % 3 - 1;
            uint32_t p = sPack[t1 * TILE_V + tid];
            int z = (int)(p >> 16) + dz, y = (int)((p >> 8) & 0xFF) + dy, x = (int)(p & 0xFF) + dx;
            int idx = -1;
            if ((unsigned)z < GD && (unsigned)y < GH && (unsigned)x < GW)
                idx = g_grid[(z * GH + y) * GW + x];
            sIdx[st ^ 1][tid] = idx;
        }

        asm volatile("fence.proxy.async.shared::cta;" ::: "memory");
        __syncthreads();

        if (tid == 0) {
            if (t == 0) {   // first use of B(k): wait its TMA
                if ((k & 1) == 0) { MBARRIER_WAIT_PARITY(mbarT0, phT0 & 1); phT0++; }
                else              { MBARRIER_WAIT_PARITY(mbarT1, phT1 & 1); phT1++; }
            }
            const uint64_t aD  = make_desc(aSm);
            const uint64_t b1D = make_desc(bSm);
            const uint64_t b2D = b1D + 512;          // +8192B in 16B units
            const uint32_t dT  = tmem + (uint32_t)(t * 64);
            const uint32_t en0 = (k == 0) ? 0u : 1u;
            #pragma unroll
            for (int q = 0; q < 4; q++)   // pass1: (ahi+alo) * whi
                mma_f16_ss(dT, aD + q * 2, b1D + q * 2, (q == 0) ? en0 : 1u);
            #pragma unroll
            for (int q = 0; q < 4; q++)   // pass2: ahi * wlo
                mma_f16_ss(dT, aD + q * 2, b2D + q * 2, 1u);
            asm volatile(
                "tcgen05.commit.cta_group::1.mbarrier::arrive::one.shared::cluster.b64 [%0];"
                :: "r"(st == 0 ? mbarM0 : mbarM1) : "memory");
        }
    }

    // Drain final commits (s=214 -> stage0, s=215 -> stage1).
    MBARRIER_WAIT_PARITY(mbarM0, phM0 & 1);
    MBARRIER_WAIT_PARITY(mbarM1, phM1 & 1);
    asm volatile("tcgen05.fence::after_thread_sync;" ::: "memory");

    // Epilogue: warpgroup 0 reads 8 accumulators (tile t at tmem + t*64).
    if (tid < 128) {
        #pragma unroll 1
        for (int t = 0; t < TGROUP; t++) {
            const uint32_t tB = tmem + (uint32_t)(t * 64);
            uint32_t r[64];
            asm volatile(
                "tcgen05.ld.sync.aligned.32x32b.x32.b32 "
                "{%0,%1,%2,%3,%4,%5,%6,%7,%8,%9,%10,%11,%12,%13,%14,%15,"
                "%16,%17,%18,%19,%20,%21,%22,%23,%24,%25,%26,%27,%28,%29,%30,%31}, [%32];"
                : "=r"(r[0]),"=r"(r[1]),"=r"(r[2]),"=r"(r[3]),"=r"(r[4]),"=r"(r[5]),"=r"(r[6]),"=r"(r[7]),
                  "=r"(r[8]),"=r"(r[9]),"=r"(r[10]),"=r"(r[11]),"=r"(r[12]),"=r"(r[13]),"=r"(r[14]),"=r"(r[15]),
                  "=r"(r[16]),"=r"(r[17]),"=r"(r[18]),"=r"(r[19]),"=r"(r[20]),"=r"(r[21]),"=r"(r[22]),"=r"(r[23]),
                  "=r"(r[24]),"=r"(r[25]),"=r"(r[26]),"=r"(r[27]),"=r"(r[28]),"=r"(r[29]),"=r"(r[30]),"=r"(r[31])
                : "r"(tB));
            asm volatile(
                "tcgen05.ld.sync.aligned.32x32b.x32.b32 "
                "{%0,%1,%2,%3,%4,%5,%6,%7,%8,%9,%10,%11,%12,%13,%14,%15,"
                "%16,%17,%18,%19,%20,%21,%22,%23,%24,%25,%26,%27,%28,%29,%30,%31}, [%32];"
                : "=r"(r[32]),"=r"(r[33]),"=r"(r[34]),"=r"(r[35]),"=r"(r[36]),"=r"(r[37]),"=r"(r[38]),"=r"(r[39]),
                  "=r"(r[40]),"=r"(r[41]),"=r"(r[42]),"=r"(r[43]),"=r"(r[44]),"=r"(r[45]),"=r"(r[46]),"=r"(r[47]),
                  "=r"(r[48]),"=r"(r[49]),"=r"(r[50]),"=r"(r[51]),"=r"(r[52]),"=r"(r[53]),"=r"(r[54]),"=r"(r[55]),
                  "=r"(r[56]),"=r"(r[57]),"=r"(r[58]),"=r"(r[59]),"=r"(r[60]),"=r"(r[61]),"=r"(r[62]),"=r"(r[63])
                : "r"(tB + 32));
            asm volatile("tcgen05.wait::ld.sync.aligned;" ::: "memory");

            int v = vBase + t * TILE_V + tid;
            if (v < n) {
                float4* op = reinterpret_cast<float4*>(out + (size_t)v * COUT);
                #pragma unroll
                for (int j = 0; j < 16; j++) {
                    float4 o;
                    o.x = __uint_as_float(r[4 * j + 0]) + sBias[4 * j + 0];
                    o.y = __uint_as_float(r[4 * j + 1]) + sBias[4 * j + 1];
                    o.z = __uint_as_float(r[4 * j + 2]) + sBias[4 * j + 2];
                    o.w = __uint_as_float(r[4 * j + 3]) + sBias[4 * j + 3];
                    op[j] = o;
                }
            }
        }
        asm volatile("tcgen05.fence::before_thread_sync;" ::: "memory");
    }

    __syncthreads();
    if (tid == 0) {
        asm volatile("mbarrier.inval.shared.b64 [%0];" :: "r"(mbarM0) : "memory");
        asm volatile("mbarrier.inval.shared.b64 [%0];" :: "r"(mbarM1) : "memory");
        asm volatile("mbarrier.inval.shared.b64 [%0];" :: "r"(mbarT0) : "memory");
        asm volatile("mbarrier.inval.shared.b64 [%0];" :: "r"(mbarT1) : "memory");
    }
    if (tid < 32) {
        asm volatile("tcgen05.dealloc.cta_group::1.sync.aligned.b32 %0, %1;" :: "r"(tmem), "r"(512u));
    }
#endif  // HAS_TCGEN05
}

extern "C" void kernel_launch(void* const* d_in, const int* in_sizes, int n_in,
                              void* d_out, int out_size) {
    const float* feat   = (const float*)d_in[0];
    const int*   coors  = (const int*)d_in[1];
    const float* weight = (const float*)d_in[2];
    const float* bias   = (const float*)d_in[3];
    float* out = (float*)d_out;
    const int n = in_sizes[0] / CIN;

    const int DYN_SMEM = 65536 + 1024;
    cudaFuncSetAttribute(conv_tc_kernel, cudaFuncAttributeMaxDynamicSharedMemorySize, DYN_SMEM);

    init_grid_kernel<<<(GD * GH * GW / 4 + 255) / 256, 256>>>();
    const int prep_threads = n * CIN + n + NK * COUT * CIN;
    prep_kernel<<<(prep_threads + 255) / 256, 256>>>(coors, feat, weight, n);
    const int nTiles  = (n + TILE_V - 1) / TILE_V;
    const int nGroups = (nTiles + TGROUP - 1) / TGROUP;
    conv_tc_kernel<<<nGroups, 256, DYN_SMEM>>>(coors, bias, out, n);
}

// round 11
// speedup vs baseline: 2.4782x; 2.4782x over previous
#include <cuda_runtime.h>
#include <cuda_bf16.h>
#include <cstdint>

#define GD 160
#define GH 160
#define GW 160
#define CIN 32
#define COUT 64
#define NK 27
#define TILE_V 128
#define TGROUP 2              // tiles per CTA (2 TMEM accumulators = 128 cols)
#define NMAX 400000

#if defined(__CUDA_ARCH_FEAT_SM103_ALL) || defined(__CUDA_ARCH_FEAT_SM100_ALL) || defined(__CUDA_ARCH_FEAT_SM101_ALL)
#define HAS_TCGEN05 1
#else
#define HAS_TCGEN05 0
#endif

// ---------------- device scratch ----------------
__device__ int      g_grid[GD * GH * GW];        // voxel -> row index
__device__ uint32_t g_packF[NMAX * CIN];         // packed (bf16 hi | lo<<16)
__device__ uint32_t g_Bw[NK * 4096];             // 27 x 16KB pre-swizzled B (pass1+pass2)

// ---------------- helpers ----------------
__device__ __forceinline__ uint32_t smem_u32(const void* p) {
    uint32_t a;
    asm("{ .reg .u64 t; cvta.to.shared.u64 t, %1; cvt.u32.u64 %0, t; }" : "=r"(a) : "l"(p));
    return a;
}

__host__ __device__ __forceinline__ uint32_t swz128(uint32_t off) {
    return off ^ ((off >> 3) & 0x70);
}

// SMEM descriptor: SW128, version=1, SBO=64 (1024B), LBO=1 (16B)
__device__ __forceinline__ uint64_t make_desc(uint32_t addr) {
    const uint64_t base =
        (uint64_t(2) << 61) | (uint64_t(1) << 46) | (uint64_t(64) << 32) | (uint64_t(1) << 16);
    return base | ((uint64_t)(addr >> 4) & 0x3FFF);
}

#define MMA_IDESC 0x8100490u   // F32 accum, A=BF16, B=BF16, N=64, M=128

#if HAS_TCGEN05
__device__ __forceinline__ void mma_f16_ss(uint32_t d_tmem, uint64_t a_desc,
                                           uint64_t b_desc, uint32_t en) {
    asm volatile(
        "{\n\t"
        ".reg .pred p;\n\t"
        "setp.ne.u32 p, %5, 0;\n\t"
        "tcgen05.mma.cta_group::1.kind::f16 [%0], %1, %2, %3, {%4, %4, %4, %4}, p;\n\t"
        "}"
        :: "r"(d_tmem), "l"(a_desc), "l"(b_desc), "r"(MMA_IDESC), "r"(0u), "r"(en)
        : "memory");
}
#endif

#define MBARRIER_WAIT_PARITY(mbar, parity) do {                                   \
    uint32_t _m = (mbar); uint32_t _p = (parity); uint32_t _done;                  \
    asm volatile(                                                                  \
        "{\n\t.reg .pred p;\n\t"                                                   \
        "mbarrier.try_wait.parity.acquire.cta.shared::cta.b64 p, [%1], %2;\n\t"    \
        "selp.b32 %0, 1, 0, p;\n\t}"                                               \
        : "=r"(_done) : "r"(_m), "r"(_p) : "memory");                              \
    if (!_done) {                                                                  \
        asm volatile(                                                              \
            "{\n\t.reg .pred P1;\n\t"                                              \
            "WL_%=:\n\t"                                                           \
            "mbarrier.try_wait.parity.acquire.cta.shared::cta.b64 P1, [%0], %1, 0x989680;\n\t" \
            "@P1 bra.uni WD_%=;\n\t"                                               \
            "bra.uni WL_%=;\n\t"                                                   \
            "WD_%=:\n\t}"                                                          \
            :: "r"(_m), "r"(_p) : "memory");                                       \
    }                                                                              \
} while (0)

// ---------------- prep kernels ----------------
__global__ void init_grid_kernel() {
    int i = blockIdx.x * blockDim.x + threadIdx.x;
    int4* p = reinterpret_cast<int4*>(g_grid);
    const int total = (GD * GH * GW) / 4;
    if (i < total) p[i] = make_int4(-1, -1, -1, -1);
}

// Fused: pack features + scatter + pack weights.
__global__ void prep_kernel(const int* __restrict__ coors,
                            const float* __restrict__ feat,
                            const float* __restrict__ weight,
                            int n) {
    int i = blockIdx.x * blockDim.x + threadIdx.x;
    const int nF = n * CIN;
    if (i < nF) {
        float x = feat[i];
        __nv_bfloat16 hi = __float2bfloat16(x);
        float r = x - __bfloat162float(hi);
        __nv_bfloat16 lo = __float2bfloat16(r);
        g_packF[i] = (uint32_t)__bfloat16_as_ushort(hi) |
                     ((uint32_t)__bfloat16_as_ushort(lo) << 16);
        return;
    }
    i -= nF;
    if (i < n) {
        int z = coors[4 * i + 1];
        int y = coors[4 * i + 2];
        int x = coors[4 * i + 3];
        g_grid[(z * GH + y) * GW + x] = i;
        return;
    }
    i -= n;
    if (i < NK * COUT * CIN) {
        int k  = i / (COUT * CIN);
        int rr = i % (COUT * CIN);
        int nn = rr / CIN;   // cout (B row)
        int c  = rr % CIN;   // cin
        float w = weight[k * CIN * COUT + c * COUT + nn];
        __nv_bfloat16 hi = __float2bfloat16(w);
        float res = w - __bfloat162float(hi);
        __nv_bfloat16 lo = __float2bfloat16(res);
        uint32_t hb = __bfloat16_as_ushort(hi);
        uint32_t lb = __bfloat16_as_ushort(lo);
        uint32_t sw = swz128((uint32_t)(nn * 128 + c * 4));
        g_Bw[k * 4096 + (sw >> 2)]        = hb | (hb << 16); // pass1: hi,hi
        g_Bw[k * 4096 + 2048 + (sw >> 2)] = lb;              // pass2: lo,0
    }
}

// ---------------- main tensor-core kernel ----------------
// K-outer / tile-inner with TGROUP=2: each CTA owns 2 tiles (256 voxels),
// 2 TMEM accumulators (128 cols -> 3 CTAs/SM still fit TMEM). B(k) TMA'd
// once per 2 MMA-steps (B L2 traffic halved vs R7). Depth-2 A pipeline;
// LDG.128+STS.128 gather; lookup prefetched one step ahead.
// Dyn smem: A0[16K] A1[16K] B0[16K] B1[16K].
__global__ __launch_bounds__(256) void conv_tc_kernel(
    const int*   __restrict__ coors,
    const float* __restrict__ bias,
    float*       __restrict__ out,
    int n)
{
#if HAS_TCGEN05
    extern __shared__ uint32_t dynsmem[];
    __shared__ uint32_t sPack[TGROUP * TILE_V];   // packed z<<16|y<<8|x (0xFFFFFFFF = inactive)
    __shared__ int   sIdx[2][TILE_V];
    __shared__ float sBias[COUT];
    __shared__ uint32_t sTmem;
    __shared__ __align__(8) uint64_t sMbarMMA[2];
    __shared__ __align__(8) uint64_t sMbarTMA[2];

    const int tid = threadIdx.x;
    const int vBase = blockIdx.x * (TGROUP * TILE_V);

    const uint32_t rawBase = smem_u32(dynsmem);
    const uint32_t aAddr   = (rawBase + 1023u) & ~1023u;
    uint32_t* sT = dynsmem + ((aAddr - rawBase) >> 2);

    const uint32_t mbarM0 = smem_u32(&sMbarMMA[0]);
    const uint32_t mbarM1 = smem_u32(&sMbarMMA[1]);
    const uint32_t mbarT0 = smem_u32(&sMbarTMA[0]);
    const uint32_t mbarT1 = smem_u32(&sMbarTMA[1]);
    if (tid == 0) {
        asm volatile("mbarrier.init.shared.b64 [%0], 1;" :: "r"(mbarM0) : "memory");
        asm volatile("mbarrier.init.shared.b64 [%0], 1;" :: "r"(mbarM1) : "memory");
        asm volatile("mbarrier.init.shared.b64 [%0], 1;" :: "r"(mbarT0) : "memory");
        asm volatile("mbarrier.init.shared.b64 [%0], 1;" :: "r"(mbarT1) : "memory");
    }
    if (tid < COUT) sBias[tid] = bias[tid];

    // Load + pack coors for the CTA's 256 voxels (z,y,x each < 160 -> 8 bits).
    {
        int slot = tid;
        int v = vBase + slot;
        uint32_t p = 0xFFFFFFFFu;
        if (v < n) {
            uint32_t z = (uint32_t)coors[4 * v + 1];
            uint32_t y = (uint32_t)coors[4 * v + 2];
            uint32_t x = (uint32_t)coors[4 * v + 3];
            p = (z << 16) | (y << 8) | x;
        }
        sPack[slot] = p;
    }
    if (tid < 32) {
        uint32_t a = smem_u32(&sTmem);
        asm volatile("tcgen05.alloc.cta_group::1.sync.aligned.shared::cta.b32 [%0], %1;"
                     :: "r"(a), "r"(128u) : "memory");
        asm volatile("tcgen05.relinquish_alloc_permit.cta_group::1.sync.aligned;");
    }
    __syncthreads();

    // Prologue lookup for step 0 (k=0: dz=dy=dx=-1, tile 0).
    if (tid < TILE_V) {
        uint32_t p = sPack[tid];
        int z = (int)(p >> 16) - 1, y = (int)((p >> 8) & 0xFF) - 1, x = (int)(p & 0xFF) - 1;
        int idx = -1;
        if ((unsigned)z < GD && (unsigned)y < GH && (unsigned)x < GW)
            idx = g_grid[(z * GH + y) * GW + x];
        sIdx[0][tid] = idx;
    }
    __syncthreads();

    const uint32_t tmem = sTmem;
    int phM0 = 0, phM1 = 0;
    int phT0 = 0, phT1 = 0;

    const int S = NK * TGROUP;   // 54 steps
    for (int s = 0; s < S; s++) {
        const int st = s & 1;
        const int k  = s >> 1;
        const int t  = s & 1;
        const uint32_t aSm = aAddr + (st ? 16384u : 0u);
        const uint32_t bSm = aAddr + 32768u + ((k & 1) ? 16384u : 0u);

        // A-stage reuse guard: MMA(s-2) done. (MMAs complete in order, so this
        // also guarantees the B stage being overwritten below has drained.)
        if (s >= 2) {
            if (st == 0) { MBARRIER_WAIT_PARITY(mbarM0, phM0 & 1); phM0++; }
            else         { MBARRIER_WAIT_PARITY(mbarM1, phM1 & 1); phM1++; }
        }

        // New k: kick B(k) TMA once (serves TGROUP steps).
        if (t == 0 && tid == 0) {
            const uint32_t mbT = (k & 1) ? mbarT1 : mbarT0;
            asm volatile(
                "mbarrier.arrive.expect_tx.shared.b64 _, [%0], %1;"
                :: "r"(mbT), "r"(16384u) : "memory");
            asm volatile(
                "cp.async.bulk.shared::cta.global.mbarrier::complete_tx::bytes "
                "[%0], [%1], %2, [%3];"
                :: "r"(bSm), "l"((const void*)(g_Bw + k * 4096)), "r"(16384u), "r"(mbT)
                : "memory");
        }

        // Vectorized gather: 1024 uint4 slots (128 rows x 8 quads), 4 per thread.
        uint4* aDst = reinterpret_cast<uint4*>(sT + ((aSm - aAddr) >> 2));
        const int* idxBuf = sIdx[st];
        #pragma unroll
        for (int ss = 0; ss < 4; ss++) {
            int slot = ss * 256 + tid;
            int v = slot >> 3;
            int q = slot & 7;
            int idx = idxBuf[v];
            uint4 val = make_uint4(0u, 0u, 0u, 0u);
            if (idx >= 0)
                val = reinterpret_cast<const uint4*>(g_packF)[idx * 8 + q];
            aDst[v * 8 + (q ^ (v & 7))] = val;
        }

        // Prefetch lookup for step s+1.
        if (s + 1 < S && tid < TILE_V) {
            const int s1 = s + 1;
            const int k1 = s1 >> 1, t1 = s1 & 1;
            const int dz = k1 / 9 - 1, dy = (k1 / 3) % 3 - 1, dx = k1 % 3 - 1;
            uint32_t p = sPack[t1 * TILE_V + tid];
            int z = (int)(p >> 16) + dz, y = (int)((p >> 8) & 0xFF) + dy, x = (int)(p & 0xFF) + dx;
            int idx = -1;
            if ((unsigned)z < GD && (unsigned)y < GH && (unsigned)x < GW)
                idx = g_grid[(z * GH + y) * GW + x];
            sIdx[st ^ 1][tid] = idx;
        }

        asm volatile("fence.proxy.async.shared::cta;" ::: "memory");
        __syncthreads();

        if (tid == 0) {
            if (t == 0) {   // first use of B(k): wait its TMA
                if ((k & 1) == 0) { MBARRIER_WAIT_PARITY(mbarT0, phT0 & 1); phT0++; }
                else              { MBARRIER_WAIT_PARITY(mbarT1, phT1 & 1); phT1++; }
            }
            const uint64_t aD  = make_desc(aSm);
            const uint64_t b1D = make_desc(bSm);
            const uint64_t b2D = b1D + 512;          // +8192B in 16B units
            const uint32_t dT  = tmem + (uint32_t)(t * 64);
            const uint32_t en0 = (k == 0) ? 0u : 1u;
            #pragma unroll
            for (int q = 0; q < 4; q++)   // pass1: (ahi+alo) * whi
                mma_f16_ss(dT, aD + q * 2, b1D + q * 2, (q == 0) ? en0 : 1u);
            #pragma unroll
            for (int q = 0; q < 4; q++)   // pass2: ahi * wlo
                mma_f16_ss(dT, aD + q * 2, b2D + q * 2, 1u);
            asm volatile(
                "tcgen05.commit.cta_group::1.mbarrier::arrive::one.shared::cluster.b64 [%0];"
                :: "r"(st == 0 ? mbarM0 : mbarM1) : "memory");
        }
    }

    // Drain final commits.
    MBARRIER_WAIT_PARITY(mbarM0, phM0 & 1);
    MBARRIER_WAIT_PARITY(mbarM1, phM1 & 1);
    asm volatile("tcgen05.fence::after_thread_sync;" ::: "memory");

    // Epilogue: warpgroup 0 reads both accumulators (tile t at tmem + t*64).
    if (tid < 128) {
        #pragma unroll 1
        for (int t = 0; t < TGROUP; t++) {
            const uint32_t tB = tmem + (uint32_t)(t * 64);
            uint32_t r[64];
            asm volatile(
                "tcgen05.ld.sync.aligned.32x32b.x32.b32 "
                "{%0,%1,%2,%3,%4,%5,%6,%7,%8,%9,%10,%11,%12,%13,%14,%15,"
                "%16,%17,%18,%19,%20,%21,%22,%23,%24,%25,%26,%27,%28,%29,%30,%31}, [%32];"
                : "=r"(r[0]),"=r"(r[1]),"=r"(r[2]),"=r"(r[3]),"=r"(r[4]),"=r"(r[5]),"=r"(r[6]),"=r"(r[7]),
                  "=r"(r[8]),"=r"(r[9]),"=r"(r[10]),"=r"(r[11]),"=r"(r[12]),"=r"(r[13]),"=r"(r[14]),"=r"(r[15]),
                  "=r"(r[16]),"=r"(r[17]),"=r"(r[18]),"=r"(r[19]),"=r"(r[20]),"=r"(r[21]),"=r"(r[22]),"=r"(r[23]),
                  "=r"(r[24]),"=r"(r[25]),"=r"(r[26]),"=r"(r[27]),"=r"(r[28]),"=r"(r[29]),"=r"(r[30]),"=r"(r[31])
                : "r"(tB));
            asm volatile(
                "tcgen05.ld.sync.aligned.32x32b.x32.b32 "
                "{%0,%1,%2,%3,%4,%5,%6,%7,%8,%9,%10,%11,%12,%13,%14,%15,"
                "%16,%17,%18,%19,%20,%21,%22,%23,%24,%25,%26,%27,%28,%29,%30,%31}, [%32];"
                : "=r"(r[32]),"=r"(r[33]),"=r"(r[34]),"=r"(r[35]),"=r"(r[36]),"=r"(r[37]),"=r"(r[38]),"=r"(r[39]),
                  "=r"(r[40]),"=r"(r[41]),"=r"(r[42]),"=r"(r[43]),"=r"(r[44]),"=r"(r[45]),"=r"(r[46]),"=r"(r[47]),
                  "=r"(r[48]),"=r"(r[49]),"=r"(r[50]),"=r"(r[51]),"=r"(r[52]),"=r"(r[53]),"=r"(r[54]),"=r"(r[55]),
                  "=r"(r[56]),"=r"(r[57]),"=r"(r[58]),"=r"(r[59]),"=r"(r[60]),"=r"(r[61]),"=r"(r[62]),"=r"(r[63])
                : "r"(tB + 32));
            asm volatile("tcgen05.wait::ld.sync.aligned;" ::: "memory");

            int v = vBase + t * TILE_V + tid;
            if (v < n) {
                float4* op = reinterpret_cast<float4*>(out + (size_t)v * COUT);
                #pragma unroll
                for (int j = 0; j < 16; j++) {
                    float4 o;
                    o.x = __uint_as_float(r[4 * j + 0]) + sBias[4 * j + 0];
                    o.y = __uint_as_float(r[4 * j + 1]) + sBias[4 * j + 1];
                    o.z = __uint_as_float(r[4 * j + 2]) + sBias[4 * j + 2];
                    o.w = __uint_as_float(r[4 * j + 3]) + sBias[4 * j + 3];
                    op[j] = o;
                }
            }
        }
        asm volatile("tcgen05.fence::before_thread_sync;" ::: "memory");
    }

    __syncthreads();
    if (tid == 0) {
        asm volatile("mbarrier.inval.shared.b64 [%0];" :: "r"(mbarM0) : "memory");
        asm volatile("mbarrier.inval.shared.b64 [%0];" :: "r"(mbarM1) : "memory");
        asm volatile("mbarrier.inval.shared.b64 [%0];" :: "r"(mbarT0) : "memory");
        asm volatile("mbarrier.inval.shared.b64 [%0];" :: "r"(mbarT1) : "memory");
    }
    if (tid < 32) {
        asm volatile("tcgen05.dealloc.cta_group::1.sync.aligned.b32 %0, %1;" :: "r"(tmem), "r"(128u));
    }
#endif  // HAS_TCGEN05
}

extern "C" void kernel_launch(void* const* d_in, const int* in_sizes, int n_in,
                              void* d_out, int out_size) {
    const float* feat   = (const float*)d_in[0];
    const int*   coors  = (const int*)d_in[1];
    const float* weight = (const float*)d_in[2];
    const float* bias   = (const float*)d_in[3];
    float* out = (float*)d_out;
    const int n = in_sizes[0] / CIN;

    const int DYN_SMEM = 65536 + 1024;
    cudaFuncSetAttribute(conv_tc_kernel, cudaFuncAttributeMaxDynamicSharedMemorySize, DYN_SMEM);

    init_grid_kernel<<<(GD * GH * GW / 4 + 255) / 256, 256>>>();
    const int prep_threads = n * CIN + n + NK * COUT * CIN;
    prep_kernel<<<(prep_threads + 255) / 256, 256>>>(coors, feat, weight, n);
    const int nTiles  = (n + TILE_V - 1) / TILE_V;
    const int nGroups = (nTiles + TGROUP - 1) / TGROUP;
    conv_tc_kernel<<<nGroups, 256, DYN_SMEM>>>(coors, bias, out, n);
}

// round 12
// speedup vs baseline: 3.2399x; 1.3074x over previous
#include <cuda_runtime.h>
#include <cuda_bf16.h>
#include <cstdint>

#define GD 160
#define GH 160
#define GW 160
#define CIN 32
#define COUT 64
#define NK 27
#define TILE_V 128
#define NMAX 400000

#if defined(__CUDA_ARCH_FEAT_SM103_ALL) || defined(__CUDA_ARCH_FEAT_SM100_ALL) || defined(__CUDA_ARCH_FEAT_SM101_ALL)
#define HAS_TCGEN05 1
#else
#define HAS_TCGEN05 0
#endif

// ---------------- device scratch ----------------
__device__ int      g_grid[GD * GH * GW];        // voxel -> row index
__device__ uint32_t g_packF[NMAX * CIN];         // packed (bf16 hi | lo<<16)
__device__ uint32_t g_Bw[NK * 4096];             // 27 x 16KB pre-swizzled B (pass1+pass2)

// ---------------- helpers ----------------
__device__ __forceinline__ uint32_t smem_u32(const void* p) {
    uint32_t a;
    asm("{ .reg .u64 t; cvta.to.shared.u64 t, %1; cvt.u32.u64 %0, t; }" : "=r"(a) : "l"(p));
    return a;
}

__host__ __device__ __forceinline__ uint32_t swz128(uint32_t off) {
    return off ^ ((off >> 3) & 0x70);
}

// SMEM descriptor: SW128, version=1, SBO=64 (1024B), LBO=1 (16B)
__device__ __forceinline__ uint64_t make_desc(uint32_t addr) {
    const uint64_t base =
        (uint64_t(2) << 61) | (uint64_t(1) << 46) | (uint64_t(64) << 32) | (uint64_t(1) << 16);
    return base | ((uint64_t)(addr >> 4) & 0x3FFF);
}

#define MMA_IDESC 0x8100490u   // F32 accum, A=BF16, B=BF16, N=64, M=128

#if HAS_TCGEN05
__device__ __forceinline__ void mma_f16_ss(uint32_t d_tmem, uint64_t a_desc,
                                           uint64_t b_desc, uint32_t en) {
    asm volatile(
        "{\n\t"
        ".reg .pred p;\n\t"
        "setp.ne.u32 p, %5, 0;\n\t"
        "tcgen05.mma.cta_group::1.kind::f16 [%0], %1, %2, %3, {%4, %4, %4, %4}, p;\n\t"
        "}"
        :: "r"(d_tmem), "l"(a_desc), "l"(b_desc), "r"(MMA_IDESC), "r"(0u), "r"(en)
        : "memory");
}
#endif

#define MBARRIER_WAIT_PARITY(mbar, parity) do {                                   \
    uint32_t _m = (mbar); uint32_t _p = (parity); uint32_t _done;                  \
    asm volatile(                                                                  \
        "{\n\t.reg .pred p;\n\t"                                                   \
        "mbarrier.try_wait.parity.acquire.cta.shared::cta.b64 p, [%1], %2;\n\t"    \
        "selp.b32 %0, 1, 0, p;\n\t}"                                               \
        : "=r"(_done) : "r"(_m), "r"(_p) : "memory");                              \
    if (!_done) {                                                                  \
        asm volatile(                                                              \
            "{\n\t.reg .pred P1;\n\t"                                              \
            "WL_%=:\n\t"                                                           \
            "mbarrier.try_wait.parity.acquire.cta.shared::cta.b64 P1, [%0], %1, 0x989680;\n\t" \
            "@P1 bra.uni WD_%=;\n\t"                                               \
            "bra.uni WL_%=;\n\t"                                                   \
            "WD_%=:\n\t}"                                                          \
            :: "r"(_m), "r"(_p) : "memory");                                       \
    }                                                                              \
} while (0)

// ---------------- prep kernels ----------------
__global__ void init_grid_kernel() {
    int i = blockIdx.x * blockDim.x + threadIdx.x;
    int4* p = reinterpret_cast<int4*>(g_grid);
    const int total = (GD * GH * GW) / 4;
    if (i < total) p[i] = make_int4(-1, -1, -1, -1);
}

// Fused: pack features + scatter + pack weights.
__global__ void prep_kernel(const int* __restrict__ coors,
                            const float* __restrict__ feat,
                            const float* __restrict__ weight,
                            int n) {
    int i = blockIdx.x * blockDim.x + threadIdx.x;
    const int nF = n * CIN;
    if (i < nF) {
        float x = feat[i];
        __nv_bfloat16 hi = __float2bfloat16(x);
        float r = x - __bfloat162float(hi);
        __nv_bfloat16 lo = __float2bfloat16(r);
        g_packF[i] = (uint32_t)__bfloat16_as_ushort(hi) |
                     ((uint32_t)__bfloat16_as_ushort(lo) << 16);
        return;
    }
    i -= nF;
    if (i < n) {
        int z = coors[4 * i + 1];
        int y = coors[4 * i + 2];
        int x = coors[4 * i + 3];
        g_grid[(z * GH + y) * GW + x] = i;
        return;
    }
    i -= n;
    if (i < NK * COUT * CIN) {
        int k  = i / (COUT * CIN);
        int rr = i % (COUT * CIN);
        int nn = rr / CIN;   // cout (B row)
        int c  = rr % CIN;   // cin
        float w = weight[k * CIN * COUT + c * COUT + nn];
        __nv_bfloat16 hi = __float2bfloat16(w);
        float res = w - __bfloat162float(hi);
        __nv_bfloat16 lo = __float2bfloat16(res);
        uint32_t hb = __bfloat16_as_ushort(hi);
        uint32_t lb = __bfloat16_as_ushort(lo);
        uint32_t sw = swz128((uint32_t)(nn * 128 + c * 4));
        g_Bw[k * 4096 + (sw >> 2)]        = hb | (hb << 16); // pass1: hi,hi
        g_Bw[k * 4096 + 2048 + (sw >> 2)] = lb;              // pass2: lo,0
    }
}

// ---------------- main tensor-core kernel ----------------
// Register-staged gather pipeline: LDG(k+1) issues right after sync(k) and
// its latency hides behind MMA issue / TMA / other CTAs; only STS(k) +
// lookup + barrier sit on the per-step critical path. Depth-2 A pipeline;
// B via TMA bulk; lookup prefetched. Dyn smem: A0[16K] A1[16K] B0[16K] B1[16K].
__global__ __launch_bounds__(256) void conv_tc_kernel(
    const int*   __restrict__ coors,
    const float* __restrict__ bias,
    float*       __restrict__ out,
    int n)
{
#if HAS_TCGEN05
    extern __shared__ uint32_t dynsmem[];
    __shared__ int   sIdx[2][TILE_V];
    __shared__ int   sZ[TILE_V], sY[TILE_V], sX[TILE_V];
    __shared__ float sBias[COUT];
    __shared__ uint32_t sTmem;
    __shared__ __align__(8) uint64_t sMbarMMA[2];
    __shared__ __align__(8) uint64_t sMbarTMA[2];

    const int tid = threadIdx.x;
    const int v0  = blockIdx.x * TILE_V;

    const uint32_t rawBase = smem_u32(dynsmem);
    const uint32_t aAddr   = (rawBase + 1023u) & ~1023u;
    uint32_t* sT = dynsmem + ((aAddr - rawBase) >> 2);

    const uint32_t mbarM0 = smem_u32(&sMbarMMA[0]);
    const uint32_t mbarM1 = smem_u32(&sMbarMMA[1]);
    const uint32_t mbarT0 = smem_u32(&sMbarTMA[0]);
    const uint32_t mbarT1 = smem_u32(&sMbarTMA[1]);
    if (tid == 0) {
        asm volatile("mbarrier.init.shared.b64 [%0], 1;" :: "r"(mbarM0) : "memory");
        asm volatile("mbarrier.init.shared.b64 [%0], 1;" :: "r"(mbarM1) : "memory");
        asm volatile("mbarrier.init.shared.b64 [%0], 1;" :: "r"(mbarT0) : "memory");
        asm volatile("mbarrier.init.shared.b64 [%0], 1;" :: "r"(mbarT1) : "memory");
    }
    if (tid < COUT) sBias[tid] = bias[tid];
    if (tid < TILE_V) {
        int v = v0 + tid;
        int z, y, x;
        if (v < n) {
            z = coors[4 * v + 1];
            y = coors[4 * v + 2];
            x = coors[4 * v + 3];
        } else {
            z = -1000; y = -1000; x = -1000;
        }
        sZ[tid] = z; sY[tid] = y; sX[tid] = x;
        int nz = z - 1, ny = y - 1, nx = x - 1;   // k=0 lookup
        int idx = -1;
        if ((unsigned)nz < GD && (unsigned)ny < GH && (unsigned)nx < GW)
            idx = g_grid[(nz * GH + ny) * GW + nx];
        sIdx[0][tid] = idx;
    }
    if (tid < 32) {
        uint32_t a = smem_u32(&sTmem);
        asm volatile("tcgen05.alloc.cta_group::1.sync.aligned.shared::cta.b32 [%0], %1;"
                     :: "r"(a), "r"(64u) : "memory");
        asm volatile("tcgen05.relinquish_alloc_permit.cta_group::1.sync.aligned;");
    }
    __syncthreads();

    const uint32_t tmem = sTmem;
    int phM0 = 0, phM1 = 0;
    int phT0 = 0, phT1 = 0;

    // Preload gather registers for k=0 (LDG issues here, consumed at STS in k=0).
    uint4 rv[4];
    {
        const int* idxBuf = sIdx[0];
        #pragma unroll
        for (int ss = 0; ss < 4; ss++) {
            int slot = ss * 256 + tid;
            int v = slot >> 3;
            int q = slot & 7;
            int idx = idxBuf[v];
            uint4 val = make_uint4(0u, 0u, 0u, 0u);
            if (idx >= 0)
                val = reinterpret_cast<const uint4*>(g_packF)[idx * 8 + q];
            rv[ss] = val;
        }
    }

    for (int k = 0; k < NK; k++) {
        const int st = k & 1;
        const uint32_t aSm = aAddr + (st ? 16384u : 0u);
        const uint32_t bSm = aAddr + 32768u + (st ? 16384u : 0u);

        // Stage reuse guard: MMA(k-2) done before overwriting A(st)/B(st).
        if (k >= 2) {
            if (st == 0) { MBARRIER_WAIT_PARITY(mbarM0, phM0 & 1); phM0++; }
            else         { MBARRIER_WAIT_PARITY(mbarM1, phM1 & 1); phM1++; }
        }

        // Kick B(k) via TMA bulk copy (async; LSU-free).
        if (tid == 0) {
            const uint32_t mbT = st == 0 ? mbarT0 : mbarT1;
            asm volatile(
                "mbarrier.arrive.expect_tx.shared.b64 _, [%0], %1;"
                :: "r"(mbT), "r"(16384u) : "memory");
            asm volatile(
                "cp.async.bulk.shared::cta.global.mbarrier::complete_tx::bytes "
                "[%0], [%1], %2, [%3];"
                :: "r"(bSm), "l"((const void*)(g_Bw + k * 4096)), "r"(16384u), "r"(mbT)
                : "memory");
        }

        // Drain staged registers into A(st): STS.128 only (LDG already landed).
        uint4* aDst = reinterpret_cast<uint4*>(sT + ((aSm - aAddr) >> 2));
        #pragma unroll
        for (int ss = 0; ss < 4; ss++) {
            int slot = ss * 256 + tid;
            int v = slot >> 3;
            int q = slot & 7;
            aDst[v * 8 + (q ^ (v & 7))] = rv[ss];
        }

        // Prefetch neighbor lookup for k+1 into the other sIdx buffer.
        if (k + 1 < NK && tid < TILE_V) {
            const int kn = k + 1;
            const int dz = kn / 9 - 1, dy = (kn / 3) % 3 - 1, dx = kn % 3 - 1;
            int z = sZ[tid] + dz, y = sY[tid] + dy, x = sX[tid] + dx;
            int idx = -1;
            if ((unsigned)z < GD && (unsigned)y < GH && (unsigned)x < GW)
                idx = g_grid[(z * GH + y) * GW + x];
            sIdx[st ^ 1][tid] = idx;
        }

        asm volatile("fence.proxy.async.shared::cta;" ::: "memory");
        __syncthreads();

        // Issue LDGs for k+1 NOW: latency overlaps MMA issue + next-step waits.
        if (k + 1 < NK) {
            const int* idxBuf = sIdx[st ^ 1];
            #pragma unroll
            for (int ss = 0; ss < 4; ss++) {
                int slot = ss * 256 + tid;
                int v = slot >> 3;
                int q = slot & 7;
                int idx = idxBuf[v];
                uint4 val = make_uint4(0u, 0u, 0u, 0u);
                if (idx >= 0)
                    val = reinterpret_cast<const uint4*>(g_packF)[idx * 8 + q];
                rv[ss] = val;
            }
        }

        if (tid == 0) {
            if (st == 0) { MBARRIER_WAIT_PARITY(mbarT0, phT0 & 1); phT0++; }
            else         { MBARRIER_WAIT_PARITY(mbarT1, phT1 & 1); phT1++; }

            const uint64_t aD  = make_desc(aSm);
            const uint64_t b1D = make_desc(bSm);
            const uint64_t b2D = b1D + 512;   // +8192B in 16B units
            #pragma unroll
            for (int s = 0; s < 4; s++)   // pass1: (ahi+alo) * whi
                mma_f16_ss(tmem, aD + s * 2, b1D + s * 2, (k == 0 && s == 0) ? 0u : 1u);
            #pragma unroll
            for (int s = 0; s < 4; s++)   // pass2: ahi * wlo
                mma_f16_ss(tmem, aD + s * 2, b2D + s * 2, 1u);
            asm volatile(
                "tcgen05.commit.cta_group::1.mbarrier::arrive::one.shared::cluster.b64 [%0];"
                :: "r"(st == 0 ? mbarM0 : mbarM1) : "memory");
        }
    }

    MBARRIER_WAIT_PARITY(mbarM1, phM1 & 1);
    MBARRIER_WAIT_PARITY(mbarM0, phM0 & 1);
    asm volatile("tcgen05.fence::after_thread_sync;" ::: "memory");

    // Epilogue: warpgroup 0 reads TMEM rows = voxels.
    if (tid < 128) {
        uint32_t r[64];
        asm volatile(
            "tcgen05.ld.sync.aligned.32x32b.x32.b32 "
            "{%0,%1,%2,%3,%4,%5,%6,%7,%8,%9,%10,%11,%12,%13,%14,%15,"
            "%16,%17,%18,%19,%20,%21,%22,%23,%24,%25,%26,%27,%28,%29,%30,%31}, [%32];"
            : "=r"(r[0]),"=r"(r[1]),"=r"(r[2]),"=r"(r[3]),"=r"(r[4]),"=r"(r[5]),"=r"(r[6]),"=r"(r[7]),
              "=r"(r[8]),"=r"(r[9]),"=r"(r[10]),"=r"(r[11]),"=r"(r[12]),"=r"(r[13]),"=r"(r[14]),"=r"(r[15]),
              "=r"(r[16]),"=r"(r[17]),"=r"(r[18]),"=r"(r[19]),"=r"(r[20]),"=r"(r[21]),"=r"(r[22]),"=r"(r[23]),
              "=r"(r[24]),"=r"(r[25]),"=r"(r[26]),"=r"(r[27]),"=r"(r[28]),"=r"(r[29]),"=r"(r[30]),"=r"(r[31])
            : "r"(tmem));
        asm volatile(
            "tcgen05.ld.sync.aligned.32x32b.x32.b32 "
            "{%0,%1,%2,%3,%4,%5,%6,%7,%8,%9,%10,%11,%12,%13,%14,%15,"
            "%16,%17,%18,%19,%20,%21,%22,%23,%24,%25,%26,%27,%28,%29,%30,%31}, [%32];"
            : "=r"(r[32]),"=r"(r[33]),"=r"(r[34]),"=r"(r[35]),"=r"(r[36]),"=r"(r[37]),"=r"(r[38]),"=r"(r[39]),
              "=r"(r[40]),"=r"(r[41]),"=r"(r[42]),"=r"(r[43]),"=r"(r[44]),"=r"(r[45]),"=r"(r[46]),"=r"(r[47]),
              "=r"(r[48]),"=r"(r[49]),"=r"(r[50]),"=r"(r[51]),"=r"(r[52]),"=r"(r[53]),"=r"(r[54]),"=r"(r[55]),
              "=r"(r[56]),"=r"(r[57]),"=r"(r[58]),"=r"(r[59]),"=r"(r[60]),"=r"(r[61]),"=r"(r[62]),"=r"(r[63])
            : "r"(tmem + 32));
        asm volatile("tcgen05.wait::ld.sync.aligned;" ::: "memory");

        int v = v0 + tid;
        if (v < n) {
            float4* op = reinterpret_cast<float4*>(out + (size_t)v * COUT);
            #pragma unroll
            for (int j = 0; j < 16; j++) {
                float4 o;
                o.x = __uint_as_float(r[4 * j + 0]) + sBias[4 * j + 0];
                o.y = __uint_as_float(r[4 * j + 1]) + sBias[4 * j + 1];
                o.z = __uint_as_float(r[4 * j + 2]) + sBias[4 * j + 2];
                o.w = __uint_as_float(r[4 * j + 3]) + sBias[4 * j + 3];
                op[j] = o;
            }
        }
    }

    __syncthreads();
    if (tid == 0) {
        asm volatile("mbarrier.inval.shared.b64 [%0];" :: "r"(mbarM0) : "memory");
        asm volatile("mbarrier.inval.shared.b64 [%0];" :: "r"(mbarM1) : "memory");
        asm volatile("mbarrier.inval.shared.b64 [%0];" :: "r"(mbarT0) : "memory");
        asm volatile("mbarrier.inval.shared.b64 [%0];" :: "r"(mbarT1) : "memory");
    }
    if (tid < 32) {
        asm volatile("tcgen05.dealloc.cta_group::1.sync.aligned.b32 %0, %1;" :: "r"(tmem), "r"(64u));
    }
#endif  // HAS_TCGEN05
}

extern "C" void kernel_launch(void* const* d_in, const int* in_sizes, int n_in,
                              void* d_out, int out_size) {
    const float* feat   = (const float*)d_in[0];
    const int*   coors  = (const int*)d_in[1];
    const float* weight = (const float*)d_in[2];
    const float* bias   = (const float*)d_in[3];
    float* out = (float*)d_out;
    const int n = in_sizes[0] / CIN;

    const int DYN_SMEM = 65536 + 1024;
    cudaFuncSetAttribute(conv_tc_kernel, cudaFuncAttributeMaxDynamicSharedMemorySize, DYN_SMEM);

    init_grid_kernel<<<(GD * GH * GW / 4 + 255) / 256, 256>>>();
    const int prep_threads = n * CIN + n + NK * COUT * CIN;
    prep_kernel<<<(prep_threads + 255) / 256, 256>>>(coors, feat, weight, n);
    conv_tc_kernel<<<(n + TILE_V - 1) / TILE_V, 256, DYN_SMEM>>>(coors, bias, out, n);
}

// round 13
// speedup vs baseline: 3.2999x; 1.0185x over previous
#include <cuda_runtime.h>
#include <cuda_fp16.h>
#include <cstdint>

#define GD 160
#define GH 160
#define GW 160
#define CIN 32
#define COUT 64
#define NK 27
#define TILE_V 128
#define NMAX 400000

#if defined(__CUDA_ARCH_FEAT_SM103_ALL) || defined(__CUDA_ARCH_FEAT_SM100_ALL) || defined(__CUDA_ARCH_FEAT_SM101_ALL)
#define HAS_TCGEN05 1
#else
#define HAS_TCGEN05 0
#endif

// ---------------- device scratch ----------------
__device__ int      g_grid[GD * GH * GW];        // voxel -> row index
__device__ __half   g_packF[NMAX * CIN];         // fp16 features (64B per voxel row)
__device__ __half   g_Bw[NK * 4096];             // 27 x 8KB pre-swizzled fp16 B tiles

// ---------------- helpers ----------------
__device__ __forceinline__ uint32_t smem_u32(const void* p) {
    uint32_t a;
    asm("{ .reg .u64 t; cvta.to.shared.u64 t, %1; cvt.u32.u64 %0, t; }" : "=r"(a) : "l"(p));
    return a;
}

__host__ __device__ __forceinline__ uint32_t swz128(uint32_t off) {
    return off ^ ((off >> 3) & 0x70);
}

// SMEM descriptor: SW128, version=1, SBO=64 (1024B), LBO=1 (16B)
__device__ __forceinline__ uint64_t make_desc(uint32_t addr) {
    const uint64_t base =
        (uint64_t(2) << 61) | (uint64_t(1) << 46) | (uint64_t(64) << 32) | (uint64_t(1) << 16);
    return base | ((uint64_t)(addr >> 4) & 0x3FFF);
}

// idesc kind::f16: accum F32 (bit4), A=F16, B=F16, N=64 (8<<17), M=128 (8<<24)
#define MMA_IDESC 0x8100010u

#if HAS_TCGEN05
__device__ __forceinline__ void mma_f16_ss(uint32_t d_tmem, uint64_t a_desc,
                                           uint64_t b_desc, uint32_t en) {
    asm volatile(
        "{\n\t"
        ".reg .pred p;\n\t"
        "setp.ne.u32 p, %5, 0;\n\t"
        "tcgen05.mma.cta_group::1.kind::f16 [%0], %1, %2, %3, {%4, %4, %4, %4}, p;\n\t"
        "}"
        :: "r"(d_tmem), "l"(a_desc), "l"(b_desc), "r"(MMA_IDESC), "r"(0u), "r"(en)
        : "memory");
}
#endif

#define MBARRIER_WAIT_PARITY(mbar, parity) do {                                   \
    uint32_t _m = (mbar); uint32_t _p = (parity); uint32_t _done;                  \
    asm volatile(                                                                  \
        "{\n\t.reg .pred p;\n\t"                                                   \
        "mbarrier.try_wait.parity.acquire.cta.shared::cta.b64 p, [%1], %2;\n\t"    \
        "selp.b32 %0, 1, 0, p;\n\t}"                                               \
        : "=r"(_done) : "r"(_m), "r"(_p) : "memory");                              \
    if (!_done) {                                                                  \
        asm volatile(                                                              \
            "{\n\t.reg .pred P1;\n\t"                                              \
            "WL_%=:\n\t"                                                           \
            "mbarrier.try_wait.parity.acquire.cta.shared::cta.b64 P1, [%0], %1, 0x989680;\n\t" \
            "@P1 bra.uni WD_%=;\n\t"                                               \
            "bra.uni WL_%=;\n\t"                                                   \
            "WD_%=:\n\t}"                                                          \
            :: "r"(_m), "r"(_p) : "memory");                                       \
    }                                                                              \
} while (0)

// ---------------- prep kernels ----------------
__global__ void init_grid_kernel() {
    int i = blockIdx.x * blockDim.x + threadIdx.x;
    int4* p = reinterpret_cast<int4*>(g_grid);
    const int total = (GD * GH * GW) / 4;
    if (i < total) p[i] = make_int4(-1, -1, -1, -1);
}

// Fused: pack features (fp16) + scatter + pack weights (fp16, pre-swizzled).
__global__ void prep_kernel(const int* __restrict__ coors,
                            const float* __restrict__ feat,
                            const float* __restrict__ weight,
                            int n) {
    int i = blockIdx.x * blockDim.x + threadIdx.x;
    const int nF = n * CIN;
    if (i < nF) {
        g_packF[i] = __float2half(feat[i]);
        return;
    }
    i -= nF;
    if (i < n) {
        int z = coors[4 * i + 1];
        int y = coors[4 * i + 2];
        int x = coors[4 * i + 3];
        g_grid[(z * GH + y) * GW + x] = i;
        return;
    }
    i -= n;
    if (i < NK * COUT * CIN) {
        int k  = i / (COUT * CIN);
        int rr = i % (COUT * CIN);
        int nn = rr / CIN;   // cout (B row)
        int c  = rr % CIN;   // cin
        float w = weight[k * CIN * COUT + c * COUT + nn];
        // B row nn: 32 fp16 K-major in first 64B of a 128B-pitch SW128 row.
        uint32_t sw = swz128((uint32_t)(nn * 128 + c * 2));
        g_Bw[k * 4096 + (sw >> 1)] = __float2half(w);
    }
}

// ---------------- main tensor-core kernel ----------------
// fp16-direct: A rows are 64B (K=32 fp16) in 128B-pitch SW128 layout; B tiles
// are 8KB; 2 MMAs per step. Register-staged gather pipeline (R12 winner):
// LDG(k+1) issued right after sync(k), STS at top of step k+1.
// Dyn smem: A0[16K] A1[16K] B0[8K] B1[8K] = 48KB -> 4 CTAs/SM.
__global__ __launch_bounds__(256) void conv_tc_kernel(
    const int*   __restrict__ coors,
    const float* __restrict__ bias,
    float*       __restrict__ out,
    int n)
{
#if HAS_TCGEN05
    extern __shared__ uint32_t dynsmem[];
    __shared__ int   sIdx[2][TILE_V];
    __shared__ int   sZ[TILE_V], sY[TILE_V], sX[TILE_V];
    __shared__ float sBias[COUT];
    __shared__ uint32_t sTmem;
    __shared__ __align__(8) uint64_t sMbarMMA[2];
    __shared__ __align__(8) uint64_t sMbarTMA[2];

    const int tid = threadIdx.x;
    const int v0  = blockIdx.x * TILE_V;

    const uint32_t rawBase = smem_u32(dynsmem);
    const uint32_t aAddr   = (rawBase + 1023u) & ~1023u;
    uint32_t* sT = dynsmem + ((aAddr - rawBase) >> 2);

    const uint32_t mbarM0 = smem_u32(&sMbarMMA[0]);
    const uint32_t mbarM1 = smem_u32(&sMbarMMA[1]);
    const uint32_t mbarT0 = smem_u32(&sMbarTMA[0]);
    const uint32_t mbarT1 = smem_u32(&sMbarTMA[1]);
    if (tid == 0) {
        asm volatile("mbarrier.init.shared.b64 [%0], 1;" :: "r"(mbarM0) : "memory");
        asm volatile("mbarrier.init.shared.b64 [%0], 1;" :: "r"(mbarM1) : "memory");
        asm volatile("mbarrier.init.shared.b64 [%0], 1;" :: "r"(mbarT0) : "memory");
        asm volatile("mbarrier.init.shared.b64 [%0], 1;" :: "r"(mbarT1) : "memory");
    }
    if (tid < COUT) sBias[tid] = bias[tid];
    if (tid < TILE_V) {
        int v = v0 + tid;
        int z, y, x;
        if (v < n) {
            z = coors[4 * v + 1];
            y = coors[4 * v + 2];
            x = coors[4 * v + 3];
        } else {
            z = -1000; y = -1000; x = -1000;
        }
        sZ[tid] = z; sY[tid] = y; sX[tid] = x;
        int nz = z - 1, ny = y - 1, nx = x - 1;   // k=0 lookup
        int idx = -1;
        if ((unsigned)nz < GD && (unsigned)ny < GH && (unsigned)nx < GW)
            idx = g_grid[(nz * GH + ny) * GW + nx];
        sIdx[0][tid] = idx;
    }
    if (tid < 32) {
        uint32_t a = smem_u32(&sTmem);
        asm volatile("tcgen05.alloc.cta_group::1.sync.aligned.shared::cta.b32 [%0], %1;"
                     :: "r"(a), "r"(64u) : "memory");
        asm volatile("tcgen05.relinquish_alloc_permit.cta_group::1.sync.aligned;");
    }
    __syncthreads();

    const uint32_t tmem = sTmem;
    int phM0 = 0, phM1 = 0;
    int phT0 = 0, phT1 = 0;

    // Preload gather registers for k=0: 512 slots (128 rows x 4 quads), 2/thread.
    uint4 rv[2];
    {
        const int* idxBuf = sIdx[0];
        #pragma unroll
        for (int ss = 0; ss < 2; ss++) {
            int slot = ss * 256 + tid;
            int v = slot >> 2;
            int q = slot & 3;
            int idx = idxBuf[v];
            uint4 val = make_uint4(0u, 0u, 0u, 0u);
            if (idx >= 0)
                val = reinterpret_cast<const uint4*>(g_packF)[idx * 4 + q];
            rv[ss] = val;
        }
    }

    for (int k = 0; k < NK; k++) {
        const int st = k & 1;
        const uint32_t aSm = aAddr + (st ? 16384u : 0u);
        const uint32_t bSm = aAddr + 32768u + (st ? 8192u : 0u);

        // Stage reuse guard: MMA(k-2) done before overwriting A(st)/B(st).
        if (k >= 2) {
            if (st == 0) { MBARRIER_WAIT_PARITY(mbarM0, phM0 & 1); phM0++; }
            else         { MBARRIER_WAIT_PARITY(mbarM1, phM1 & 1); phM1++; }
        }

        // Kick B(k) via TMA bulk copy (8KB, async, LSU-free).
        if (tid == 0) {
            const uint32_t mbT = st == 0 ? mbarT0 : mbarT1;
            asm volatile(
                "mbarrier.arrive.expect_tx.shared.b64 _, [%0], %1;"
                :: "r"(mbT), "r"(8192u) : "memory");
            asm volatile(
                "cp.async.bulk.shared::cta.global.mbarrier::complete_tx::bytes "
                "[%0], [%1], %2, [%3];"
                :: "r"(bSm), "l"((const void*)(g_Bw + k * 4096)), "r"(8192u), "r"(mbT)
                : "memory");
        }

        // Drain staged registers into A(st): STS.128 only. Logical quad q (0..3)
        // of row v lands at swizzled quad q^(v&7) within the 128B row.
        uint4* aDst = reinterpret_cast<uint4*>(sT + ((aSm - aAddr) >> 2));
        #pragma unroll
        for (int ss = 0; ss < 2; ss++) {
            int slot = ss * 256 + tid;
            int v = slot >> 2;
            int q = slot & 3;
            aDst[v * 8 + (q ^ (v & 7))] = rv[ss];
        }

        // Prefetch neighbor lookup for k+1 into the other sIdx buffer.
        if (k + 1 < NK && tid < TILE_V) {
            const int kn = k + 1;
            const int dz = kn / 9 - 1, dy = (kn / 3) % 3 - 1, dx = kn % 3 - 1;
            int z = sZ[tid] + dz, y = sY[tid] + dy, x = sX[tid] + dx;
            int idx = -1;
            if ((unsigned)z < GD && (unsigned)y < GH && (unsigned)x < GW)
                idx = g_grid[(z * GH + y) * GW + x];
            sIdx[st ^ 1][tid] = idx;
        }

        asm volatile("fence.proxy.async.shared::cta;" ::: "memory");
        __syncthreads();

        // Issue LDGs for k+1 NOW: latency overlaps MMA issue + next-step waits.
        if (k + 1 < NK) {
            const int* idxBuf = sIdx[st ^ 1];
            #pragma unroll
            for (int ss = 0; ss < 2; ss++) {
                int slot = ss * 256 + tid;
                int v = slot >> 2;
                int q = slot & 3;
                int idx = idxBuf[v];
                uint4 val = make_uint4(0u, 0u, 0u, 0u);
                if (idx >= 0)
                    val = reinterpret_cast<const uint4*>(g_packF)[idx * 4 + q];
                rv[ss] = val;
            }
        }

        if (tid == 0) {
            if (st == 0) { MBARRIER_WAIT_PARITY(mbarT0, phT0 & 1); phT0++; }
            else         { MBARRIER_WAIT_PARITY(mbarT1, phT1 & 1); phT1++; }

            const uint64_t aD = make_desc(aSm);
            const uint64_t bD = make_desc(bSm);
            // K=32 fp16 -> 2 MMAs of K=16 (desc step +2 = 32B).
            mma_f16_ss(tmem, aD,     bD,     (k == 0) ? 0u : 1u);
            mma_f16_ss(tmem, aD + 2, bD + 2, 1u);
            asm volatile(
                "tcgen05.commit.cta_group::1.mbarrier::arrive::one.shared::cluster.b64 [%0];"
                :: "r"(st == 0 ? mbarM0 : mbarM1) : "memory");
        }
    }

    MBARRIER_WAIT_PARITY(mbarM1, phM1 & 1);
    MBARRIER_WAIT_PARITY(mbarM0, phM0 & 1);
    asm volatile("tcgen05.fence::after_thread_sync;" ::: "memory");

    // Epilogue: warpgroup 0 reads TMEM rows = voxels.
    if (tid < 128) {
        uint32_t r[64];
        asm volatile(
            "tcgen05.ld.sync.aligned.32x32b.x32.b32 "
            "{%0,%1,%2,%3,%4,%5,%6,%7,%8,%9,%10,%11,%12,%13,%14,%15,"
            "%16,%17,%18,%19,%20,%21,%22,%23,%24,%25,%26,%27,%28,%29,%30,%31}, [%32];"
            : "=r"(r[0]),"=r"(r[1]),"=r"(r[2]),"=r"(r[3]),"=r"(r[4]),"=r"(r[5]),"=r"(r[6]),"=r"(r[7]),
              "=r"(r[8]),"=r"(r[9]),"=r"(r[10]),"=r"(r[11]),"=r"(r[12]),"=r"(r[13]),"=r"(r[14]),"=r"(r[15]),
              "=r"(r[16]),"=r"(r[17]),"=r"(r[18]),"=r"(r[19]),"=r"(r[20]),"=r"(r[21]),"=r"(r[22]),"=r"(r[23]),
              "=r"(r[24]),"=r"(r[25]),"=r"(r[26]),"=r"(r[27]),"=r"(r[28]),"=r"(r[29]),"=r"(r[30]),"=r"(r[31])
            : "r"(tmem));
        asm volatile(
            "tcgen05.ld.sync.aligned.32x32b.x32.b32 "
            "{%0,%1,%2,%3,%4,%5,%6,%7,%8,%9,%10,%11,%12,%13,%14,%15,"
            "%16,%17,%18,%19,%20,%21,%22,%23,%24,%25,%26,%27,%28,%29,%30,%31}, [%32];"
            : "=r"(r[32]),"=r"(r[33]),"=r"(r[34]),"=r"(r[35]),"=r"(r[36]),"=r"(r[37]),"=r"(r[38]),"=r"(r[39]),
              "=r"(r[40]),"=r"(r[41]),"=r"(r[42]),"=r"(r[43]),"=r"(r[44]),"=r"(r[45]),"=r"(r[46]),"=r"(r[47]),
              "=r"(r[48]),"=r"(r[49]),"=r"(r[50]),"=r"(r[51]),"=r"(r[52]),"=r"(r[53]),"=r"(r[54]),"=r"(r[55]),
              "=r"(r[56]),"=r"(r[57]),"=r"(r[58]),"=r"(r[59]),"=r"(r[60]),"=r"(r[61]),"=r"(r[62]),"=r"(r[63])
            : "r"(tmem + 32));
        asm volatile("tcgen05.wait::ld.sync.aligned;" ::: "memory");

        int v = v0 + tid;
        if (v < n) {
            float4* op = reinterpret_cast<float4*>(out + (size_t)v * COUT);
            #pragma unroll
            for (int j = 0; j < 16; j++) {
                float4 o;
                o.x = __uint_as_float(r[4 * j + 0]) + sBias[4 * j + 0];
                o.y = __uint_as_float(r[4 * j + 1]) + sBias[4 * j + 1];
                o.z = __uint_as_float(r[4 * j + 2]) + sBias[4 * j + 2];
                o.w = __uint_as_float(r[4 * j + 3]) + sBias[4 * j + 3];
                op[j] = o;
            }
        }
    }

    __syncthreads();
    if (tid == 0) {
        asm volatile("mbarrier.inval.shared.b64 [%0];" :: "r"(mbarM0) : "memory");
        asm volatile("mbarrier.inval.shared.b64 [%0];" :: "r"(mbarM1) : "memory");
        asm volatile("mbarrier.inval.shared.b64 [%0];" :: "r"(mbarT0) : "memory");
        asm volatile("mbarrier.inval.shared.b64 [%0];" :: "r"(mbarT1) : "memory");
    }
    if (tid < 32) {
        asm volatile("tcgen05.dealloc.cta_group::1.sync.aligned.b32 %0, %1;" :: "r"(tmem), "r"(64u));
    }
#endif  // HAS_TCGEN05
}

extern "C" void kernel_launch(void* const* d_in, const int* in_sizes, int n_in,
                              void* d_out, int out_size) {
    const float* feat   = (const float*)d_in[0];
    const int*   coors  = (const int*)d_in[1];
    const float* weight = (const float*)d_in[2];
    const float* bias   = (const float*)d_in[3];
    float* out = (float*)d_out;
    const int n = in_sizes[0] / CIN;

    const int DYN_SMEM = 49152 + 1024;   // A 2x16KB + B 2x8KB + alignment slack
    cudaFuncSetAttribute(conv_tc_kernel, cudaFuncAttributeMaxDynamicSharedMemorySize, DYN_SMEM);

    init_grid_kernel<<<(GD * GH * GW / 4 + 255) / 256, 256>>>();
    const int prep_threads = n * CIN + n + NK * COUT * CIN;
    prep_kernel<<<(prep_threads + 255) / 256, 256>>>(coors, feat, weight, n);
    conv_tc_kernel<<<(n + TILE_V - 1) / TILE_V, 256, DYN_SMEM>>>(coors, bias, out, n);
}

// round 14
// speedup vs baseline: 4.8675x; 1.4750x over previous
#include <cuda_runtime.h>
#include <cuda_fp16.h>
#include <cstdint>

#define GD 160
#define GH 160
#define GW 160
#define CIN 32
#define COUT 64
#define NK 27
#define TILE_V 128
#define NMAX 400000

#if defined(__CUDA_ARCH_FEAT_SM103_ALL) || defined(__CUDA_ARCH_FEAT_SM100_ALL) || defined(__CUDA_ARCH_FEAT_SM101_ALL)
#define HAS_TCGEN05 1
#else
#define HAS_TCGEN05 0
#endif

// ---------------- device scratch ----------------
__device__ int      g_grid[GD * GH * GW];        // voxel -> row index
__device__ __half   g_packF[NMAX * CIN];         // fp16 features (64B per voxel row)
__device__ __half   g_Bw[NK * 4096];             // 27 x 8KB pre-swizzled fp16 B tiles

// ---------------- helpers ----------------
__device__ __forceinline__ uint32_t smem_u32(const void* p) {
    uint32_t a;
    asm("{ .reg .u64 t; cvta.to.shared.u64 t, %1; cvt.u32.u64 %0, t; }" : "=r"(a) : "l"(p));
    return a;
}

__host__ __device__ __forceinline__ uint32_t swz128(uint32_t off) {
    return off ^ ((off >> 3) & 0x70);
}

// SMEM descriptor: SW128, version=1, SBO=64 (1024B), LBO=1 (16B)
__device__ __forceinline__ uint64_t make_desc(uint32_t addr) {
    const uint64_t base =
        (uint64_t(2) << 61) | (uint64_t(1) << 46) | (uint64_t(64) << 32) | (uint64_t(1) << 16);
    return base | ((uint64_t)(addr >> 4) & 0x3FFF);
}

// idesc kind::f16: accum F32 (bit4), A=F16, B=F16, N=64 (8<<17), M=128 (8<<24)
#define MMA_IDESC 0x8100010u

#if HAS_TCGEN05
__device__ __forceinline__ void mma_f16_ss(uint32_t d_tmem, uint64_t a_desc,
                                           uint64_t b_desc, uint32_t en) {
    asm volatile(
        "{\n\t"
        ".reg .pred p;\n\t"
        "setp.ne.u32 p, %5, 0;\n\t"
        "tcgen05.mma.cta_group::1.kind::f16 [%0], %1, %2, %3, {%4, %4, %4, %4}, p;\n\t"
        "}"
        :: "r"(d_tmem), "l"(a_desc), "l"(b_desc), "r"(MMA_IDESC), "r"(0u), "r"(en)
        : "memory");
}
#endif

#define MBARRIER_WAIT_PARITY(mbar, parity) do {                                   \
    uint32_t _m = (mbar); uint32_t _p = (parity); uint32_t _done;                  \
    asm volatile(                                                                  \
        "{\n\t.reg .pred p;\n\t"                                                   \
        "mbarrier.try_wait.parity.acquire.cta.shared::cta.b64 p, [%1], %2;\n\t"    \
        "selp.b32 %0, 1, 0, p;\n\t}"                                               \
        : "=r"(_done) : "r"(_m), "r"(_p) : "memory");                              \
    if (!_done) {                                                                  \
        asm volatile(                                                              \
            "{\n\t.reg .pred P1;\n\t"                                              \
            "WL_%=:\n\t"                                                           \
            "mbarrier.try_wait.parity.acquire.cta.shared::cta.b64 P1, [%0], %1, 0x989680;\n\t" \
            "@P1 bra.uni WD_%=;\n\t"                                               \
            "bra.uni WL_%=;\n\t"                                                   \
            "WD_%=:\n\t}"                                                          \
            :: "r"(_m), "r"(_p) : "memory");                                       \
    }                                                                              \
} while (0)

// ---------------- prep kernels ----------------
__global__ void init_grid_kernel() {
    int i = blockIdx.x * blockDim.x + threadIdx.x;
    int4* p = reinterpret_cast<int4*>(g_grid);
    const int total = (GD * GH * GW) / 4;
    if (i < total) p[i] = make_int4(-1, -1, -1, -1);
}

// Fused: pack features (fp16) + scatter + pack weights (fp16, pre-swizzled).
__global__ void prep_kernel(const int* __restrict__ coors,
                            const float* __restrict__ feat,
                            const float* __restrict__ weight,
                            int n) {
    int i = blockIdx.x * blockDim.x + threadIdx.x;
    const int nF = n * CIN;
    if (i < nF) {
        g_packF[i] = __float2half(feat[i]);
        return;
    }
    i -= nF;
    if (i < n) {
        int z = coors[4 * i + 1];
        int y = coors[4 * i + 2];
        int x = coors[4 * i + 3];
        g_grid[(z * GH + y) * GW + x] = i;
        return;
    }
    i -= n;
    if (i < NK * COUT * CIN) {
        int k  = i / (COUT * CIN);
        int rr = i % (COUT * CIN);
        int nn = rr / CIN;   // cout (B row)
        int c  = rr % CIN;   // cin
        float w = weight[k * CIN * COUT + c * COUT + nn];
        uint32_t sw = swz128((uint32_t)(nn * 128 + c * 2));
        g_Bw[k * 4096 + (sw >> 1)] = __float2half(w);
    }
}

// ---------------- main tensor-core kernel ----------------
// Distance-2 register-staged pipeline for BOTH gather data and grid lookup:
//   post-sync(k): issue gather-LDG(k+1) [reads sIdx] and lookup-LDG(k+2) -> rIdx
//   step k+1 body: STS rv -> A, STS rIdx -> sIdx[(k+2)&1]
// No global-load latency remains on the inter-sync critical path.
// Dyn smem: A0[16K] A1[16K] B0[8K] B1[8K] = 48KB -> 4 CTAs/SM.
__global__ __launch_bounds__(256) void conv_tc_kernel(
    const int*   __restrict__ coors,
    const float* __restrict__ bias,
    float*       __restrict__ out,
    int n)
{
#if HAS_TCGEN05
    extern __shared__ uint32_t dynsmem[];
    __shared__ int   sIdx[2][TILE_V];
    __shared__ int   sZ[TILE_V], sY[TILE_V], sX[TILE_V];
    __shared__ float sBias[COUT];
    __shared__ uint32_t sTmem;
    __shared__ __align__(8) uint64_t sMbarMMA[2];
    __shared__ __align__(8) uint64_t sMbarTMA[2];

    const int tid = threadIdx.x;
    const int v0  = blockIdx.x * TILE_V;

    const uint32_t rawBase = smem_u32(dynsmem);
    const uint32_t aAddr   = (rawBase + 1023u) & ~1023u;
    uint32_t* sT = dynsmem + ((aAddr - rawBase) >> 2);

    const uint32_t mbarM0 = smem_u32(&sMbarMMA[0]);
    const uint32_t mbarM1 = smem_u32(&sMbarMMA[1]);
    const uint32_t mbarT0 = smem_u32(&sMbarTMA[0]);
    const uint32_t mbarT1 = smem_u32(&sMbarTMA[1]);
    if (tid == 0) {
        asm volatile("mbarrier.init.shared.b64 [%0], 1;" :: "r"(mbarM0) : "memory");
        asm volatile("mbarrier.init.shared.b64 [%0], 1;" :: "r"(mbarM1) : "memory");
        asm volatile("mbarrier.init.shared.b64 [%0], 1;" :: "r"(mbarT0) : "memory");
        asm volatile("mbarrier.init.shared.b64 [%0], 1;" :: "r"(mbarT1) : "memory");
    }
    if (tid < COUT) sBias[tid] = bias[tid];
    if (tid < TILE_V) {
        int v = v0 + tid;
        int z, y, x;
        if (v < n) {
            z = coors[4 * v + 1];
            y = coors[4 * v + 2];
            x = coors[4 * v + 3];
        } else {
            z = -1000; y = -1000; x = -1000;
        }
        sZ[tid] = z; sY[tid] = y; sX[tid] = x;
        int nz = z - 1, ny = y - 1, nx = x - 1;   // k=0 lookup (dz=dy=dx=-1)
        int idx = -1;
        if ((unsigned)nz < GD && (unsigned)ny < GH && (unsigned)nx < GW)
            idx = g_grid[(nz * GH + ny) * GW + nx];
        sIdx[1][tid] = idx;   // buffer parity for k=0 is (0+0... use [1] see below)
    }
    if (tid < 32) {
        uint32_t a = smem_u32(&sTmem);
        asm volatile("tcgen05.alloc.cta_group::1.sync.aligned.shared::cta.b32 [%0], %1;"
                     :: "r"(a), "r"(64u) : "memory");
        asm volatile("tcgen05.relinquish_alloc_permit.cta_group::1.sync.aligned;");
    }
    __syncthreads();

    const uint32_t tmem = sTmem;
    int phM0 = 0, phM1 = 0;
    int phT0 = 0, phT1 = 0;

    // Buffer convention: gather for step k reads sIdx[k & 1].
    // (k=0 lookup stored to sIdx[1]... fix: read buffer is (k&1)^1 so k=0 -> [1].)
    // Preload rv(0) from sIdx[1]; issue lookup-LDG(1) -> rIdx.
    uint4 rv[2];
    {
        const int* idxBuf = sIdx[1];
        #pragma unroll
        for (int ss = 0; ss < 2; ss++) {
            int slot = ss * 256 + tid;
            int v = slot >> 2;
            int q = slot & 3;
            int idx = idxBuf[v];
            uint4 val = make_uint4(0u, 0u, 0u, 0u);
            if (idx >= 0)
                val = reinterpret_cast<const uint4*>(g_packF)[idx * 4 + q];
            rv[ss] = val;
        }
    }
    int rIdx = -1;
    if (tid < TILE_V) {   // lookup for k=1: dz=-1, dy=-1, dx=0
        int z = sZ[tid] - 1, y = sY[tid] - 1, x = sX[tid];
        if ((unsigned)z < GD && (unsigned)y < GH && (unsigned)x < GW)
            rIdx = g_grid[(z * GH + y) * GW + x];
    }

    for (int k = 0; k < NK; k++) {
        const int st = k & 1;
        const uint32_t aSm = aAddr + (st ? 16384u : 0u);
        const uint32_t bSm = aAddr + 32768u + (st ? 8192u : 0u);

        // Stage reuse guard: MMA(k-2) done before overwriting A(st)/B(st).
        if (k >= 2) {
            if (st == 0) { MBARRIER_WAIT_PARITY(mbarM0, phM0 & 1); phM0++; }
            else         { MBARRIER_WAIT_PARITY(mbarM1, phM1 & 1); phM1++; }
        }

        // Kick B(k) via TMA bulk copy (8KB, async, LSU-free).
        if (tid == 0) {
            const uint32_t mbT = st == 0 ? mbarT0 : mbarT1;
            asm volatile(
                "mbarrier.arrive.expect_tx.shared.b64 _, [%0], %1;"
                :: "r"(mbT), "r"(8192u) : "memory");
            asm volatile(
                "cp.async.bulk.shared::cta.global.mbarrier::complete_tx::bytes "
                "[%0], [%1], %2, [%3];"
                :: "r"(bSm), "l"((const void*)(g_Bw + k * 4096)), "r"(8192u), "r"(mbT)
                : "memory");
        }

        // Drain staged gather registers into A(st): STS.128 only.
        uint4* aDst = reinterpret_cast<uint4*>(sT + ((aSm - aAddr) >> 2));
        #pragma unroll
        for (int ss = 0; ss < 2; ss++) {
            int slot = ss * 256 + tid;
            int v = slot >> 2;
            int q = slot & 3;
            aDst[v * 8 + (q ^ (v & 7))] = rv[ss];
        }

        // Drain staged lookup register for k+1 into sIdx[(k+1)^1... buffer (k+1)&1^1].
        // Read side uses sIdx[(k+1)&1 ^ 1] == sIdx[st]: write where step k+1 reads.
        if (k + 1 < NK && tid < TILE_V)
            sIdx[st][tid] = rIdx;   // step k+1 reads sIdx[(k+1)&1 ^ 1] = sIdx[st]

        asm volatile("fence.proxy.async.shared::cta;" ::: "memory");
        __syncthreads();

        // Issue gather LDGs for k+1 (reads sIdx[st], just published).
        if (k + 1 < NK) {
            const int* idxBuf = sIdx[st];
            #pragma unroll
            for (int ss = 0; ss < 2; ss++) {
                int slot = ss * 256 + tid;
                int v = slot >> 2;
                int q = slot & 3;
                int idx = idxBuf[v];
                uint4 val = make_uint4(0u, 0u, 0u, 0u);
                if (idx >= 0)
                    val = reinterpret_cast<const uint4*>(g_packF)[idx * 4 + q];
                rv[ss] = val;
            }
        }

        // Issue lookup LDG for k+2 into rIdx (landed by step k+1 body).
        if (k + 2 < NK && tid < TILE_V) {
            const int kn = k + 2;
            const int dz = kn / 9 - 1, dy = (kn / 3) % 3 - 1, dx = kn % 3 - 1;
            int z = sZ[tid] + dz, y = sY[tid] + dy, x = sX[tid] + dx;
            int idx = -1;
            if ((unsigned)z < GD && (unsigned)y < GH && (unsigned)x < GW)
                idx = g_grid[(z * GH + y) * GW + x];
            rIdx = idx;
        }

        if (tid == 0) {
            if (st == 0) { MBARRIER_WAIT_PARITY(mbarT0, phT0 & 1); phT0++; }
            else         { MBARRIER_WAIT_PARITY(mbarT1, phT1 & 1); phT1++; }

            const uint64_t aD = make_desc(aSm);
            const uint64_t bD = make_desc(bSm);
            mma_f16_ss(tmem, aD,     bD,     (k == 0) ? 0u : 1u);
            mma_f16_ss(tmem, aD + 2, bD + 2, 1u);
            asm volatile(
                "tcgen05.commit.cta_group::1.mbarrier::arrive::one.shared::cluster.b64 [%0];"
                :: "r"(st == 0 ? mbarM0 : mbarM1) : "memory");
        }
    }

    MBARRIER_WAIT_PARITY(mbarM1, phM1 & 1);
    MBARRIER_WAIT_PARITY(mbarM0, phM0 & 1);
    asm volatile("tcgen05.fence::after_thread_sync;" ::: "memory");

    // Epilogue: warpgroup 0 reads TMEM rows = voxels.
    if (tid < 128) {
        uint32_t r[64];
        asm volatile(
            "tcgen05.ld.sync.aligned.32x32b.x32.b32 "
            "{%0,%1,%2,%3,%4,%5,%6,%7,%8,%9,%10,%11,%12,%13,%14,%15,"
            "%16,%17,%18,%19,%20,%21,%22,%23,%24,%25,%26,%27,%28,%29,%30,%31}, [%32];"
            : "=r"(r[0]),"=r"(r[1]),"=r"(r[2]),"=r"(r[3]),"=r"(r[4]),"=r"(r[5]),"=r"(r[6]),"=r"(r[7]),
              "=r"(r[8]),"=r"(r[9]),"=r"(r[10]),"=r"(r[11]),"=r"(r[12]),"=r"(r[13]),"=r"(r[14]),"=r"(r[15]),
              "=r"(r[16]),"=r"(r[17]),"=r"(r[18]),"=r"(r[19]),"=r"(r[20]),"=r"(r[21]),"=r"(r[22]),"=r"(r[23]),
              "=r"(r[24]),"=r"(r[25]),"=r"(r[26]),"=r"(r[27]),"=r"(r[28]),"=r"(r[29]),"=r"(r[30]),"=r"(r[31])
            : "r"(tmem));
        asm volatile(
            "tcgen05.ld.sync.aligned.32x32b.x32.b32 "
            "{%0,%1,%2,%3,%4,%5,%6,%7,%8,%9,%10,%11,%12,%13,%14,%15,"
            "%16,%17,%18,%19,%20,%21,%22,%23,%24,%25,%26,%27,%28,%29,%30,%31}, [%32];"
            : "=r"(r[32]),"=r"(r[33]),"=r"(r[34]),"=r"(r[35]),"=r"(r[36]),"=r"(r[37]),"=r"(r[38]),"=r"(r[39]),
              "=r"(r[40]),"=r"(r[41]),"=r"(r[42]),"=r"(r[43]),"=r"(r[44]),"=r"(r[45]),"=r"(r[46]),"=r"(r[47]),
              "=r"(r[48]),"=r"(r[49]),"=r"(r[50]),"=r"(r[51]),"=r"(r[52]),"=r"(r[53]),"=r"(r[54]),"=r"(r[55]),
              "=r"(r[56]),"=r"(r[57]),"=r"(r[58]),"=r"(r[59]),"=r"(r[60]),"=r"(r[61]),"=r"(r[62]),"=r"(r[63])
            : "r"(tmem + 32));
        asm volatile("tcgen05.wait::ld.sync.aligned;" ::: "memory");

        int v = v0 + tid;
        if (v < n) {
            float4* op = reinterpret_cast<float4*>(out + (size_t)v * COUT);
            #pragma unroll
            for (int j = 0; j < 16; j++) {
                float4 o;
                o.x = __uint_as_float(r[4 * j + 0]) + sBias[4 * j + 0];
                o.y = __uint_as_float(r[4 * j + 1]) + sBias[4 * j + 1];
                o.z = __uint_as_float(r[4 * j + 2]) + sBias[4 * j + 2];
                o.w = __uint_as_float(r[4 * j + 3]) + sBias[4 * j + 3];
                op[j] = o;
            }
        }
    }

    __syncthreads();
    if (tid == 0) {
        asm volatile("mbarrier.inval.shared.b64 [%0];" :: "r"(mbarM0) : "memory");
        asm volatile("mbarrier.inval.shared.b64 [%0];" :: "r"(mbarM1) : "memory");
        asm volatile("mbarrier.inval.shared.b64 [%0];" :: "r"(mbarT0) : "memory");
        asm volatile("mbarrier.inval.shared.b64 [%0];" :: "r"(mbarT1) : "memory");
    }
    if (tid < 32) {
        asm volatile("tcgen05.dealloc.cta_group::1.sync.aligned.b32 %0, %1;" :: "r"(tmem), "r"(64u));
    }
#endif  // HAS_TCGEN05
}

extern "C" void kernel_launch(void* const* d_in, const int* in_sizes, int n_in,
                              void* d_out, int out_size) {
    const float* feat   = (const float*)d_in[0];
    const int*   coors  = (const int*)d_in[1];
    const float* weight = (const float*)d_in[2];
    const float* bias   = (const float*)d_in[3];
    float* out = (float*)d_out;
    const int n = in_sizes[0] / CIN;

    const int DYN_SMEM = 49152 + 1024;   // A 2x16KB + B 2x8KB + alignment slack
    cudaFuncSetAttribute(conv_tc_kernel, cudaFuncAttributeMaxDynamicSharedMemorySize, DYN_SMEM);

    init_grid_kernel<<<(GD * GH * GW / 4 + 255) / 256, 256>>>();
    const int prep_threads = n * CIN + n + NK * COUT * CIN;
    prep_kernel<<<(prep_threads + 255) / 256, 256>>>(coors, feat, weight, n);
    conv_tc_kernel<<<(n + TILE_V - 1) / TILE_V, 256, DYN_SMEM>>>(coors, bias, out, n);
}